// round 14
// baseline (speedup 1.0000x reference)
#include <cuda_runtime.h>
#include <stdint.h>

// Problem shape (fixed by the reference): x is (T, B, 1) fp32, lr scalar.
#define T_DIM 8192
#define B_DIM 4096
#define S_CHUNKS 64
#define CH 128          // T_DIM / S_CHUNKS
#define NWORDS 4        // CH / 32

// Scratch (device globals). Chunk-major, coalesced over b.
__device__ float4 g_coef [S_CHUNKS * B_DIM];  // (A0, C0, A1, C1) per (s,b)   4 MB
__device__ uint4  g_bits [S_CHUNKS * B_DIM];  // 128 packed x bits per (s,b)  4 MB
__device__ float  g_xprev[S_CHUNKS * B_DIM];  // x[t0-1] per (s,b)            1 MB
__device__ float4 g_state[S_CHUNKS * B_DIM];  // (p0, p1, xprev, -) entry     4 MB

__device__ __forceinline__ float clamp_lr(const float* lrp) {
    return fminf(fmaxf(*lrp, 0.0f), 1.0f);
}

// r^n, n in [0,128], square-and-multiply (no smem, no syncs).
__device__ __forceinline__ float rpow_int(float r, int n) {
    float res = 1.0f, base = r;
    #pragma unroll
    for (int i = 0; i < 8; i++) {
        res  = ((n >> i) & 1) ? res * base : res;
        base = base * base;
    }
    return res;
}

// ---------------------------------------------------------------------------
// Pass 1 (best measured: plain LDG, 27.1us, regs 32, occ ~74%): per (chunk s,
// column b), one column per thread (262144 threads). Streams x once, packs
// bits to registers; chunk multiplier A = r^(#updates) via popcount of the
// obs_prev bit stream; additive C term per-step FMA:
//   pb==0: C0 = C0*r + lr*x_t    pb==1: C1 = C1*r + lr*x_t
// ---------------------------------------------------------------------------
__global__ void __launch_bounds__(256) pass1_kernel(
    const float* __restrict__ x, const float* __restrict__ lrp)
{
    const int b = blockIdx.x * blockDim.x + threadIdx.x;
    const int s = blockIdx.y;
    const float lr = clamp_lr(lrp);
    const float r  = 1.0f - lr;

    const float* xp = x + (size_t)(s * CH) * B_DIM + b;

    const float xprev = (s == 0) ? 0.0f : xp[-(ptrdiff_t)B_DIM];
    g_xprev[s * B_DIM + b] = xprev;
    bool pb = (xprev != 0.0f);

    float C0 = 0.0f, C1 = 0.0f;
    uint32_t W[NWORDS];

    #pragma unroll
    for (int h = 0; h < NWORDS; h++) {
        uint32_t w = 0;
        #pragma unroll
        for (int i0 = 0; i0 < 32; i0 += 8) {
            float xv[8];                               // 8-deep LDG batch
            #pragma unroll
            for (int j = 0; j < 8; j++)
                xv[j] = xp[(size_t)(h * 32 + i0 + j) * B_DIM];
            #pragma unroll
            for (int j = 0; j < 8; j++) {
                const float v  = xv[j];
                const bool  xb = (v != 0.0f);
                const float t  = v * lr;               // exact: x in {0,1}
                C0 = pb ? C0 : fmaf(C0, r, t);
                C1 = pb ? fmaf(C1, r, t) : C1;
                w  = xb ? (w | (1u << (i0 + j))) : w;
                pb = xb;
            }
        }
        W[h] = w;
    }

    // obs_prev stream over the chunk = [xprev, x_0 .. x_126]
    const int ones = __popc(W[0]) + __popc(W[1]) + __popc(W[2]) + __popc(W[3]);
    const int n1   = ones - (int)(W[3] >> 31) + (xprev != 0.0f ? 1 : 0);

    g_coef[s * B_DIM + b] = make_float4(rpow_int(r, CH - n1), C0,
                                        rpow_int(r, n1),      C1);
    g_bits[s * B_DIM + b] = make_uint4(W[0], W[1], W[2], W[3]);
}

// ---------------------------------------------------------------------------
// Scan: one thread per column; 64 sequential affine compositions (coef is
// L2-resident after pass1 in the real, unflushed run). Emits a float4 entry
// record (p0, p1, xprev, 0) so pass2 needs a single LDG.128 prologue load.
// The xprev gather is off the serial FMA chain and pipelines freely.
// ---------------------------------------------------------------------------
__global__ void __launch_bounds__(256) scan_kernel()
{
    const int b = blockIdx.x * blockDim.x + threadIdx.x;
    float p0 = 0.5f, p1 = 0.5f;
    #pragma unroll 8
    for (int s = 0; s < S_CHUNKS; s++) {
        const float4 c  = g_coef [s * B_DIM + b];
        const float  xp = g_xprev[s * B_DIM + b];
        g_state[s * B_DIM + b] = make_float4(p0, p1, xp, 0.0f);
        p0 = fmaf(p0, c.x, c.y);
        p1 = fmaf(p1, c.z, c.w);
    }
}

// ---------------------------------------------------------------------------
// Pass 2 (best measured of six variants: lean selected/other step, ~31.7us):
// pa = lineage selected by pb, po = the other; the step's output IS the next
// step's selected state:
//   u  = fma(r, pa, xb ? lr : 0) ; sw = (xb == pb)
//   pa' = sw ? u : po ; po' = sw ? po : u ; store pa'
// ~7 instructions per output including the store. Single float4 prologue.
// ---------------------------------------------------------------------------
__global__ void __launch_bounds__(256) pass2_kernel(
    float* __restrict__ out, const float* __restrict__ lrp)
{
    const int b = blockIdx.x * blockDim.x + threadIdx.x;
    const int s = blockIdx.y;
    const float lr = clamp_lr(lrp);
    const float r  = 1.0f - lr;

    float* op = out + (size_t)(s * CH) * B_DIM + b;

    const float4 st = g_state[s * B_DIM + b];      // p0, p1, xprev
    const uint4  bw = g_bits [s * B_DIM + b];
    const uint32_t W[NWORDS] = { bw.x, bw.y, bw.z, bw.w };
    bool pb = (st.z != 0.0f);

    float pa = pb ? st.y : st.x;     // selected lineage
    float po = pb ? st.x : st.y;     // other lineage

    #pragma unroll
    for (int wi = 0; wi < NWORDS; wi++) {
        const uint32_t w = W[wi];
        #pragma unroll
        for (int i = 0; i < 32; i++) {
            const bool  xb  = (w >> i) & 1u;
            const float add = xb ? lr : 0.0f;
            const float u   = fmaf(r, pa, add);
            const bool  sw  = (xb == pb);
            const float npa = sw ? u  : po;
            po              = sw ? po : u;
            pa = npa;
            op[(size_t)(wi * 32 + i) * B_DIM] = pa;   // output == next selected
            pb = xb;
        }
    }
}

extern "C" void kernel_launch(void* const* d_in, const int* in_sizes, int n_in,
                              void* d_out, int out_size)
{
    const float* x  = (const float*)d_in[0];
    const float* lr = (const float*)d_in[1];
    if (n_in >= 2 && in_sizes[0] == 1) { x = (const float*)d_in[1]; lr = (const float*)d_in[0]; }

    dim3 blk(256);

    pass1_kernel<<<dim3(B_DIM / 256, S_CHUNKS), blk>>>(x, lr);
    scan_kernel<<<B_DIM / 256, blk>>>();
    pass2_kernel<<<dim3(B_DIM / 256, S_CHUNKS), blk>>>((float*)d_out, lr);
}

// round 15
// speedup vs baseline: 1.1241x; 1.1241x over previous
#include <cuda_runtime.h>
#include <stdint.h>

// Problem shape (fixed by the reference): x is (T, B, 1) fp32, lr scalar.
#define T_DIM 8192
#define B_DIM 4096
#define S_CHUNKS 64
#define CH 128          // T_DIM / S_CHUNKS
#define NWORDS 4        // CH / 32

// Scratch (device globals). Chunk-major, coalesced over b.
__device__ float4 g_coef [S_CHUNKS * B_DIM];  // (A0, C0, A1, C1) per (s,b)   4 MB
__device__ uint4  g_bits [S_CHUNKS * B_DIM];  // 128 packed x bits per (s,b)  4 MB
__device__ float  g_xprev[S_CHUNKS * B_DIM];  // x[t0-1] per (s,b)            1 MB
__device__ float2 g_state[S_CHUNKS * B_DIM];  // (p0,p1) entering chunk       2 MB

__device__ __forceinline__ float clamp_lr(const float* lrp) {
    return fminf(fmaxf(*lrp, 0.0f), 1.0f);
}

// r^n, n in [0,128], square-and-multiply (no smem, no syncs).
__device__ __forceinline__ float rpow_int(float r, int n) {
    float res = 1.0f, base = r;
    #pragma unroll
    for (int i = 0; i < 8; i++) {
        res  = ((n >> i) & 1) ? res * base : res;
        base = base * base;
    }
    return res;
}

// ---------------------------------------------------------------------------
// Pass 1 (R10 champion config): per (chunk s, column b), one column per
// thread (262144 threads). Streams x once with __ldcs; bits packed to
// registers; chunk multiplier A = r^(#updates) via popcount of the obs_prev
// bit stream; additive C term per-step FMA:
//   pb==0: C0 = C0*r + lr*x_t    pb==1: C1 = C1*r + lr*x_t
// ---------------------------------------------------------------------------
__global__ void __launch_bounds__(256) pass1_kernel(
    const float* __restrict__ x, const float* __restrict__ lrp)
{
    const int b = blockIdx.x * blockDim.x + threadIdx.x;
    const int s = blockIdx.y;
    const float lr = clamp_lr(lrp);
    const float r  = 1.0f - lr;

    const float* xp = x + (size_t)(s * CH) * B_DIM + b;

    const float xprev = (s == 0) ? 0.0f : __ldcs(xp - B_DIM);
    g_xprev[s * B_DIM + b] = xprev;
    bool pb = (xprev != 0.0f);

    float C0 = 0.0f, C1 = 0.0f;
    uint32_t W[NWORDS];

    #pragma unroll
    for (int h = 0; h < NWORDS; h++) {
        uint32_t w = 0;
        #pragma unroll
        for (int i0 = 0; i0 < 32; i0 += 8) {
            float xv[8];                               // 8-deep LDG batch
            #pragma unroll
            for (int j = 0; j < 8; j++)
                xv[j] = __ldcs(&xp[(size_t)(h * 32 + i0 + j) * B_DIM]);
            #pragma unroll
            for (int j = 0; j < 8; j++) {
                const float v  = xv[j];
                const bool  xb = (v != 0.0f);
                const float t  = v * lr;              // exact: x in {0,1}
                C0 = pb ? C0 : fmaf(C0, r, t);
                C1 = pb ? fmaf(C1, r, t) : C1;
                w  = xb ? (w | (1u << (i0 + j))) : w;
                pb = xb;
            }
        }
        W[h] = w;
    }

    const int ones = __popc(W[0]) + __popc(W[1]) + __popc(W[2]) + __popc(W[3]);
    const int n1   = ones - (int)(W[3] >> 31) + (xprev != 0.0f ? 1 : 0);

    g_coef[s * B_DIM + b] = make_float4(rpow_int(r, CH - n1), C0,
                                        rpow_int(r, n1),      C1);
    g_bits[s * B_DIM + b] = make_uint4(W[0], W[1], W[2], W[3]);
}

// ---------------------------------------------------------------------------
// Scan (R4/R10 form — proven ~3.5us): one thread per column, 64 sequential
// affine compositions; coef data L2-resident after pass1.
// ---------------------------------------------------------------------------
__global__ void __launch_bounds__(256) scan_kernel()
{
    const int b = blockIdx.x * blockDim.x + threadIdx.x;
    float p0 = 0.5f, p1 = 0.5f;
    #pragma unroll 8
    for (int s = 0; s < S_CHUNKS; s++) {
        const float4 c = g_coef[s * B_DIM + b];
        g_state[s * B_DIM + b] = make_float2(p0, p1);
        p0 = fmaf(p0, c.x, c.y);
        p1 = fmaf(p1, c.z, c.w);
    }
}

// ---------------------------------------------------------------------------
// Pass 2 (R10 lean step — best measured): selected/other representation.
// pa = state selected by pb (the lineage being updated), po = the other.
// The step's output IS the next step's pa:
//   u  = fma(r, pa, xb ? lr : 0)      (update of lineage pb)
//   sw = (xb == pb)
//   pa' = sw ? u : po ; po' = sw ? po : u ; store pa'
// ~7 instructions per output including the store.
// ---------------------------------------------------------------------------
__global__ void __launch_bounds__(256) pass2_kernel(
    float* __restrict__ out, const float* __restrict__ lrp)
{
    const int b = blockIdx.x * blockDim.x + threadIdx.x;
    const int s = blockIdx.y;
    const float lr = clamp_lr(lrp);
    const float r  = 1.0f - lr;

    float* op = out + (size_t)(s * CH) * B_DIM + b;

    const float2 st = g_state[s * B_DIM + b];
    const uint4  bw = g_bits [s * B_DIM + b];
    const uint32_t W[NWORDS] = { bw.x, bw.y, bw.z, bw.w };
    bool pb = (g_xprev[s * B_DIM + b] != 0.0f);

    float pa = pb ? st.y : st.x;     // selected lineage
    float po = pb ? st.x : st.y;     // other lineage

    #pragma unroll
    for (int wi = 0; wi < NWORDS; wi++) {
        const uint32_t w = W[wi];
        #pragma unroll
        for (int i = 0; i < 32; i++) {
            const bool  xb  = (w >> i) & 1u;          // LOP3 -> predicate
            const float add = xb ? lr : 0.0f;
            const float u   = fmaf(r, pa, add);
            const bool  sw  = (xb == pb);             // PLOP3
            const float npa = sw ? u  : po;
            po              = sw ? po : u;
            pa = npa;
            op[(size_t)(wi * 32 + i) * B_DIM] = pa;   // output == next selected
            pb = xb;
        }
    }
}

extern "C" void kernel_launch(void* const* d_in, const int* in_sizes, int n_in,
                              void* d_out, int out_size)
{
    const float* x  = (const float*)d_in[0];
    const float* lr = (const float*)d_in[1];
    if (n_in >= 2 && in_sizes[0] == 1) { x = (const float*)d_in[1]; lr = (const float*)d_in[0]; }

    dim3 blk(256);

    pass1_kernel<<<dim3(B_DIM / 256, S_CHUNKS), blk>>>(x, lr);
    scan_kernel<<<B_DIM / 256, blk>>>();
    pass2_kernel<<<dim3(B_DIM / 256, S_CHUNKS), blk>>>((float*)d_out, lr);
}

// round 16
// speedup vs baseline: 1.1286x; 1.0040x over previous
#include <cuda_runtime.h>
#include <stdint.h>

// Problem shape (fixed by the reference): x is (T, B, 1) fp32, lr scalar.
#define T_DIM 8192
#define B_DIM 4096
#define S_CHUNKS 64
#define CH 128          // T_DIM / S_CHUNKS
#define NWORDS 4        // CH / 32

// Scratch (device globals). Chunk-major, coalesced over b.
__device__ float4 g_coef [S_CHUNKS * B_DIM];  // (A0, C0, A1, C1) per (s,b)   4 MB
__device__ uint4  g_bits [S_CHUNKS * B_DIM];  // 128 packed x bits per (s,b)  4 MB
__device__ float  g_xprev[S_CHUNKS * B_DIM];  // x[t0-1] per (s,b)            1 MB
__device__ float2 g_state[S_CHUNKS * B_DIM];  // (p0,p1) entering chunk       2 MB

__device__ __forceinline__ float clamp_lr(const float* lrp) {
    return fminf(fmaxf(*lrp, 0.0f), 1.0f);
}

// r^n, n in [0,128], square-and-multiply (no smem, no syncs).
__device__ __forceinline__ float rpow_int(float r, int n) {
    float res = 1.0f, base = r;
    #pragma unroll
    for (int i = 0; i < 8; i++) {
        res  = ((n >> i) & 1) ? res * base : res;
        base = base * base;
    }
    return res;
}

// ---------------------------------------------------------------------------
// Pass 1 (champion config): per (chunk s, column b), one column per thread
// (262144 threads, ~27-30us read-capped at ~5.1TB/s). Streams x once; bits
// packed to registers; chunk multiplier A = r^(#updates) via popcount of the
// obs_prev bit stream; additive C term per-step FMA:
//   pb==0: C0 = C0*r + lr*x_t    pb==1: C1 = C1*r + lr*x_t
// ---------------------------------------------------------------------------
__global__ void __launch_bounds__(256) pass1_kernel(
    const float* __restrict__ x, const float* __restrict__ lrp)
{
    const int b = blockIdx.x * blockDim.x + threadIdx.x;
    const int s = blockIdx.y;
    const float lr = clamp_lr(lrp);
    const float r  = 1.0f - lr;

    const float* xp = x + (size_t)(s * CH) * B_DIM + b;

    const float xprev = (s == 0) ? 0.0f : __ldcs(xp - B_DIM);
    g_xprev[s * B_DIM + b] = xprev;
    bool pb = (xprev != 0.0f);

    float C0 = 0.0f, C1 = 0.0f;
    uint32_t W[NWORDS];

    #pragma unroll
    for (int h = 0; h < NWORDS; h++) {
        uint32_t w = 0;
        #pragma unroll
        for (int i0 = 0; i0 < 32; i0 += 8) {
            float xv[8];                               // 8-deep LDG batch
            #pragma unroll
            for (int j = 0; j < 8; j++)
                xv[j] = __ldcs(&xp[(size_t)(h * 32 + i0 + j) * B_DIM]);
            #pragma unroll
            for (int j = 0; j < 8; j++) {
                const float v  = xv[j];
                const bool  xb = (v != 0.0f);
                const float t  = v * lr;              // exact: x in {0,1}
                C0 = pb ? C0 : fmaf(C0, r, t);
                C1 = pb ? fmaf(C1, r, t) : C1;
                w  = xb ? (w | (1u << (i0 + j))) : w;
                pb = xb;
            }
        }
        W[h] = w;
    }

    const int ones = __popc(W[0]) + __popc(W[1]) + __popc(W[2]) + __popc(W[3]);
    const int n1   = ones - (int)(W[3] >> 31) + (xprev != 0.0f ? 1 : 0);

    g_coef[s * B_DIM + b] = make_float4(rpow_int(r, CH - n1), C0,
                                        rpow_int(r, n1),      C1);
    g_bits[s * B_DIM + b] = make_uint4(W[0], W[1], W[2], W[3]);
}

// ---------------------------------------------------------------------------
// Scan (proven ~3.5us): one thread per column, 64 sequential affine
// compositions; coef data L2-resident after pass1 in the real (unflushed)
// run. Stores (p0,p1) entering each chunk.
// ---------------------------------------------------------------------------
__global__ void __launch_bounds__(256) scan_kernel()
{
    const int b = blockIdx.x * blockDim.x + threadIdx.x;
    float p0 = 0.5f, p1 = 0.5f;
    #pragma unroll 8
    for (int s = 0; s < S_CHUNKS; s++) {
        const float4 c = g_coef[s * B_DIM + b];
        g_state[s * B_DIM + b] = make_float2(p0, p1);
        p0 = fmaf(p0, c.x, c.y);
        p1 = fmaf(p1, c.z, c.w);
    }
}

// ---------------------------------------------------------------------------
// Pass 2 (lean selected/other step — best measured of six variants):
// pa = state selected by pb (the lineage being updated), po = the other.
// The step's output IS the next step's pa:
//   u  = fma(r, pa, xb ? lr : 0)      (update of lineage pb)
//   sw = (xb == pb)
//   pa' = sw ? u : po ; po' = sw ? po : u ; store pa'
// ~7 instructions per output including the store; write-capped at ~4TB/s.
// ---------------------------------------------------------------------------
__global__ void __launch_bounds__(256) pass2_kernel(
    float* __restrict__ out, const float* __restrict__ lrp)
{
    const int b = blockIdx.x * blockDim.x + threadIdx.x;
    const int s = blockIdx.y;
    const float lr = clamp_lr(lrp);
    const float r  = 1.0f - lr;

    float* op = out + (size_t)(s * CH) * B_DIM + b;

    const float2 st = g_state[s * B_DIM + b];
    const uint4  bw = g_bits [s * B_DIM + b];
    const uint32_t W[NWORDS] = { bw.x, bw.y, bw.z, bw.w };
    bool pb = (g_xprev[s * B_DIM + b] != 0.0f);

    float pa = pb ? st.y : st.x;     // selected lineage
    float po = pb ? st.x : st.y;     // other lineage

    #pragma unroll
    for (int wi = 0; wi < NWORDS; wi++) {
        const uint32_t w = W[wi];
        #pragma unroll
        for (int i = 0; i < 32; i++) {
            const bool  xb  = (w >> i) & 1u;          // LOP3 -> predicate
            const float add = xb ? lr : 0.0f;
            const float u   = fmaf(r, pa, add);
            const bool  sw  = (xb == pb);             // PLOP3
            const float npa = sw ? u  : po;
            po              = sw ? po : u;
            pa = npa;
            op[(size_t)(wi * 32 + i) * B_DIM] = pa;   // output == next selected
            pb = xb;
        }
    }
}

extern "C" void kernel_launch(void* const* d_in, const int* in_sizes, int n_in,
                              void* d_out, int out_size)
{
    const float* x  = (const float*)d_in[0];
    const float* lr = (const float*)d_in[1];
    if (n_in >= 2 && in_sizes[0] == 1) { x = (const float*)d_in[1]; lr = (const float*)d_in[0]; }

    dim3 blk(256);

    pass1_kernel<<<dim3(B_DIM / 256, S_CHUNKS), blk>>>(x, lr);
    scan_kernel<<<B_DIM / 256, blk>>>();
    pass2_kernel<<<dim3(B_DIM / 256, S_CHUNKS), blk>>>((float*)d_out, lr);
}